// round 12
// baseline (speedup 1.0000x reference)
#include <cuda_runtime.h>
#include <cuda_fp16.h>
#include <math.h>
#include <stdint.h>

// Problem constants (fixed: S=1024, B=16, I=D=1024, L=2)
#define S_LEN 1024
#define BATCH 16
#define DIM   1024
#define GDIM  (4 * DIM)       // 4096
#define KDIM  1024
#define MROWS (S_LEN * BATCH) // 16384
#define EPS 1e-6f

// ---------------------------------------------------------------------------
// Device scratch (no allocation allowed in kernel_launch)
// ---------------------------------------------------------------------------
__device__ __half g_pre[(size_t)S_LEN * BATCH * GDIM];  // 134 MB (NO bias; fp16)
__device__ __half g_ah[(size_t)MROWS * KDIM];           // 33.5 MB (A in fp16)
__device__ __half g_wh0[(size_t)GDIM * KDIM];           // 8.4 MB  (W0 fp16)
__device__ __half g_wh1[(size_t)GDIM * KDIM];           // 8.4 MB  (W1 fp16)
__device__ int    g_flags[2 * 128];                     // per-layer M-block counters

// ---------------------------------------------------------------------------
// PTX helpers — base-target only (NO tcgen05: harness emits compute_103 PTX)
// ---------------------------------------------------------------------------
__device__ __forceinline__ uint32_t smem_u32(const void* p) {
    uint32_t a;
    asm("{ .reg .u64 t; cvta.to.shared.u64 t, %1; cvt.u32.u64 %0, t; }"
        : "=r"(a) : "l"(p));
    return a;
}
__device__ __forceinline__ void cp16(uint32_t dst, const void* src) {
    asm volatile("cp.async.cg.shared.global [%0], [%1], 16;"
                 :: "r"(dst), "l"(src));
}
__device__ __forceinline__ void ldsm_x4(uint32_t& r0, uint32_t& r1,
                                        uint32_t& r2, uint32_t& r3,
                                        uint32_t addr) {
    asm volatile("ldmatrix.sync.aligned.m8n8.x4.shared.b16 {%0,%1,%2,%3}, [%4];"
                 : "=r"(r0), "=r"(r1), "=r"(r2), "=r"(r3) : "r"(addr));
}
__device__ __forceinline__ void mma_f16(float* d, const uint32_t* a,
                                        uint32_t b0, uint32_t b1) {
    asm volatile(
        "mma.sync.aligned.m16n8k16.row.col.f32.f16.f16.f32 "
        "{%0,%1,%2,%3}, {%4,%5,%6,%7}, {%8,%9}, {%0,%1,%2,%3};"
        : "+f"(d[0]), "+f"(d[1]), "+f"(d[2]), "+f"(d[3])
        : "r"(a[0]), "r"(a[1]), "r"(a[2]), "r"(a[3]), "r"(b0), "r"(b1));
}

// Fast math (rel err ~2^-21; far under the 1e-3 budget)
__device__ __forceinline__ float fast_sigmoid(float x) {
    return __fdividef(1.0f, 1.0f + __expf(-x));
}
__device__ __forceinline__ float fast_tanh(float x) {
    float e = __expf(2.0f * x);
    return __fdividef(e - 1.0f, e + 1.0f);
}

// Swizzle: rows are 64B (32 fp16); XOR the 16B-segment index with (row>>1)&3
__device__ __forceinline__ uint32_t swz_addr(uint32_t plane_base, int row, int seg) {
    return plane_base + (uint32_t)(row * 64) + ((uint32_t)((seg ^ ((row >> 1) & 3)) << 4));
}

// ---------------------------------------------------------------------------
// fp32 -> fp16 convert kernel. n multiple of 4.
// ---------------------------------------------------------------------------
__global__ __launch_bounds__(256)
void convert_kernel(const float* __restrict__ src,
                    __half* __restrict__ dst, int n)
{
    int i = (blockIdx.x * 256 + threadIdx.x) * 4;
    if (i >= n) return;
    float4 v = *reinterpret_cast<const float4*>(src + i);
    __half2* d2 = reinterpret_cast<__half2*>(dst + i);
    d2[0] = __half2(__float2half(v.x), __float2half(v.y));
    d2[1] = __half2(__float2half(v.z), __float2half(v.w));
}

// ---------------------------------------------------------------------------
// Fused GEMM + scan kernel (one per layer).
// CTAs [0, 4096): R11 GEMM — CTA 128x128, 4 warps (2Mx2N, 64x64 warp tiles),
//   K-chunk 32, 4-stage cp.async pipeline, 2 CTAs/SM. After the epilogue each
//   CTA bumps flags[m] (m = M-block). pre = A @ W^T, fp16, no bias.
// CTAs [4096, 4224): the sLSTM scan (128 lanes/CTA). Scan chunk k (16 steps)
//   reads exactly M-blocks 2k,2k+1 of pre, so it spin-waits on those flags
//   before each cp.async prefetch. Scheduled last -> overlaps the GEMM tail.
//   Layer 0 writes h as fp16 into ah (rows of completed M-blocks only — safe).
// ---------------------------------------------------------------------------
#define KCHUNK 32
#define NCHUNK (KDIM / KCHUNK)       // 32
#define PLANE  8192                  // 128 rows * 64 bytes
#define STAGE_BYTES (2 * PLANE)      // [A, W] = 16 KB
#define STAGES 4
#define FUSED_SMEM (STAGES * STAGE_BYTES)  // 64 KB (scan reuses: needs 48 KB)
#define GEMM_CTAS 4096
#define SCAN_CTAS 128
#define CH 16
#define NCH (S_LEN / CH)             // 64 chunks

__device__ __forceinline__ void gemm_load_chunk(uint32_t stage_base,
                                                const __half* Ap,
                                                const __half* Wp,
                                                int k0, int tid)
{
#pragma unroll
    for (int p = 0; p < 2; p++) {
        const __half* src = (p == 0) ? Ap : Wp;
#pragma unroll
        for (int h = 0; h < 4; h++) {
            int it = tid + h * 128;          // 0..511
            int row = it >> 2;
            int seg = it & 3;
            cp16(swz_addr(stage_base + p * PLANE, row, seg),
                 src + (size_t)row * KDIM + k0 + seg * 8);
        }
    }
}

__device__ __forceinline__ void wait_mblock(volatile const int* f, int k) {
    while (f[2 * k] < 32 || f[2 * k + 1] < 32) { __nanosleep(64); }
}

template <bool EMIT_HALF>
__global__ __launch_bounds__(128, 2)
void fused_kernel(const __half* __restrict__ Ah,      // GEMM A [MROWS, K]
                  const __half* __restrict__ Wh,      // GEMM W [GDIM, K]
                  __half* __restrict__ pre,           // [S,B,4D] out/in
                  const float* __restrict__ bias,     // [4D]
                  const float* __restrict__ r,        // [4D]
                  const float* __restrict__ h0,       // [L,B,D]
                  const float* __restrict__ extra0,   // [L,B,3D]
                  int layer,
                  float* __restrict__ out_f32,        // [S,B,D] (or null)
                  __half* __restrict__ out_h16,       // [S,B,D] (or null)
                  float* __restrict__ hf,             // [L,B,D]
                  float* __restrict__ extraf,         // [L,B,3D]
                  int* __restrict__ flags)            // [128]
{
    extern __shared__ __align__(1024) char smem[];
    const int tid = threadIdx.x;

    if (blockIdx.x < GEMM_CTAS) {
        // ================= GEMM part (R11, unchanged math) =================
        const uint32_t sbase = smem_u32(smem);
        const int wid  = tid >> 5;      // 0..3
        const int lane = tid & 31;
        const int warp_m = wid & 1;
        const int warp_n = wid >> 1;
        const int mblk = blockIdx.x >> 5;         // 0..127
        const int bm = mblk * 128;
        const int bn = (blockIdx.x & 31) * 128;

        const __half* Ap = Ah + (size_t)bm * KDIM;
        const __half* Wp = Wh + (size_t)bn * KDIM;

        float acc[4][8][4];
#pragma unroll
        for (int i = 0; i < 4; i++)
#pragma unroll
            for (int j = 0; j < 8; j++)
#pragma unroll
                for (int k = 0; k < 4; k++) acc[i][j][k] = 0.0f;

        gemm_load_chunk(sbase + 0 * STAGE_BYTES, Ap, Wp, 0 * KCHUNK, tid);
        asm volatile("cp.async.commit_group;");
        gemm_load_chunk(sbase + 1 * STAGE_BYTES, Ap, Wp, 1 * KCHUNK, tid);
        asm volatile("cp.async.commit_group;");
        gemm_load_chunk(sbase + 2 * STAGE_BYTES, Ap, Wp, 2 * KCHUNK, tid);
        asm volatile("cp.async.commit_group;");

        const int a_lrow = lane & 15;
        const int a_lseg = lane >> 4;
        const int b_lrow = (lane & 7) + ((lane >> 4) << 3);
        const int b_lseg = (lane >> 3) & 1;

        for (int i = 0; i < NCHUNK; i++) {
            const int rem = NCHUNK - 1 - i;
            if (rem >= 2)      { asm volatile("cp.async.wait_group 2;"); }
            else if (rem == 1) { asm volatile("cp.async.wait_group 1;"); }
            else               { asm volatile("cp.async.wait_group 0;"); }
            __syncthreads();

            if (i + 3 < NCHUNK) {
                gemm_load_chunk(sbase + (uint32_t)((i + 3) % STAGES) * STAGE_BYTES,
                                Ap, Wp, (i + 3) * KCHUNK, tid);
                asm volatile("cp.async.commit_group;");
            }

            const uint32_t st = sbase + (uint32_t)(i % STAGES) * STAGE_BYTES;
            const uint32_t base_a = st;
            const uint32_t base_w = st + PLANE;

#pragma unroll
            for (int ks = 0; ks < 2; ks++) {
                uint32_t a[4][4], w[4][4];
#pragma unroll
                for (int jj = 0; jj < 4; jj++) {
                    int row = warp_n * 64 + jj * 16 + b_lrow;
                    ldsm_x4(w[jj][0], w[jj][1], w[jj][2], w[jj][3],
                            swz_addr(base_w, row, ks * 2 + b_lseg));
                }
#pragma unroll
                for (int ti = 0; ti < 4; ti++) {
                    int row = warp_m * 64 + ti * 16 + a_lrow;
                    ldsm_x4(a[ti][0], a[ti][1], a[ti][2], a[ti][3],
                            swz_addr(base_a, row, ks * 2 + a_lseg));
                }
#pragma unroll
                for (int ti = 0; ti < 4; ti++)
#pragma unroll
                    for (int jj = 0; jj < 4; jj++) {
                        mma_f16(acc[ti][2 * jj + 0], a[ti], w[jj][0], w[jj][1]);
                        mma_f16(acc[ti][2 * jj + 1], a[ti], w[jj][2], w[jj][3]);
                    }
            }
        }

        // Epilogue: fp16 streaming stores
        const int mrow0 = bm + warp_m * 64 + (lane >> 2);
        const int col0  = bn + warp_n * 64 + (lane & 3) * 2;
#pragma unroll
        for (int ti = 0; ti < 4; ti++) {
            const int r0 = mrow0 + ti * 16;
#pragma unroll
            for (int g = 0; g < 8; g++) {
                int col = col0 + g * 8;
                __half2 v0 = __floats2half2_rn(acc[ti][g][0], acc[ti][g][1]);
                __half2 v1 = __floats2half2_rn(acc[ti][g][2], acc[ti][g][3]);
                __stcs(reinterpret_cast<__half2*>(pre + (size_t)r0 * GDIM + col), v0);
                __stcs(reinterpret_cast<__half2*>(pre + (size_t)(r0 + 8) * GDIM + col), v1);
            }
        }

        // Publish completion of this (m, n) CTA.
        __threadfence();
        __syncthreads();
        if (tid == 0) atomicAdd(&flags[mblk], 1);
        return;
    }

    // ======================= Scan part (128 lanes/CTA) =====================
    __half (*buf)[CH][4][128] = reinterpret_cast<__half (*)[CH][4][128]>(smem);
    volatile const int* vflags = flags;

    const int sidx = blockIdx.x - GEMM_CTAS;      // 0..127
    const int ltid = tid;                         // 0..127
    const int L0 = sidx * 128;
    const int b  = L0 >> 10;
    const int d0 = L0 & (DIM - 1);
    const int d  = d0 + ltid;

    const float rz = r[0 * DIM + d];
    const float ri = r[1 * DIM + d];
    const float rf = r[2 * DIM + d];
    const float ro = r[3 * DIM + d];
    const float bz = bias[0 * DIM + d];
    const float bi = bias[1 * DIM + d];
    const float bf = bias[2 * DIM + d];
    const float bo = bias[3 * DIM + d];
    const bool rzero = (rz == 0.0f) && (ri == 0.0f) && (rf == 0.0f) && (ro == 0.0f);

    const size_t lbd  = (size_t)layer * BATCH * DIM + (size_t)b * DIM;
    const size_t lb3d = (size_t)layer * BATCH * 3 * DIM + (size_t)b * 3 * DIM;

    float h = h0[lbd + d];
    float c = extra0[lb3d + 0 * DIM + d];
    float n = extra0[lb3d + 1 * DIM + d];
    float m = extra0[lb3d + 2 * DIM + d];

    // Prefetch mapping: seg = 16B chunk (0..15), gate (0..3), sh = step parity.
    // 4 gates x 16 segs x 16 steps = 1024 cp16 per chunk / 128 thr = 8 each.
    const int seg  = ltid & 15;
    const int gate = (ltid >> 4) & 3;
    const int sh   = ltid >> 6;
    const size_t strideT = (size_t)BATCH * GDIM;
    const __half* src0 = pre + (size_t)b * GDIM + (size_t)gate * DIM + d0 + seg * 8;

#define SCAN_PREFETCH(stage, k)                                               \
    do {                                                                      \
        const __half* _s = src0 + ((size_t)(k) * CH + sh) * strideT;          \
        _Pragma("unroll")                                                     \
        for (int _jj = 0; _jj < CH / 2; _jj++) {                              \
            cp16(smem_u32(&buf[stage][2 * _jj + sh][gate][seg * 8]), _s);     \
            _s += 2 * strideT;                                                \
        }                                                                     \
        asm volatile("cp.async.commit_group;");                               \
    } while (0)

    wait_mblock(vflags, 0); __threadfence();
    SCAN_PREFETCH(0, 0);
    wait_mblock(vflags, 1); __threadfence();
    SCAN_PREFETCH(1, 1);
    wait_mblock(vflags, 2); __threadfence();
    SCAN_PREFETCH(2, 2);

    size_t outIdx = (size_t)b * DIM + d;
    const size_t strideO = (size_t)BATCH * DIM;

    for (int k = 0; k < NCH; k++) {
        if (k + 2 < NCH)      { asm volatile("cp.async.wait_group 2;"); }
        else if (k + 1 < NCH) { asm volatile("cp.async.wait_group 1;"); }
        else                  { asm volatile("cp.async.wait_group 0;"); }
        __syncthreads();

        const int cur = k % 3;

        if (rzero) {
            float zt[CH], ot[CH];
#pragma unroll
            for (int j = 0; j < CH; j++) {
                zt[j] = fast_tanh(__half2float(buf[cur][j][0][ltid]) + bz);
                ot[j] = fast_sigmoid(__half2float(buf[cur][j][3][ltid]) + bo);
            }
#pragma unroll
            for (int j = 0; j < CH; j++) {
                const float ip = __half2float(buf[cur][j][1][ltid]) + bi;
                const float fm = __half2float(buf[cur][j][2][ltid]) + bf + m;
                const float mn = fmaxf(fm, ip);
                const float ft = __expf(fm - mn);
                const float it = __expf(ip - mn);
                c = ft * c + it * zt[j];
                n = ft * n + it;
                m = mn;
                h = ot[j] * __fdividef(c, fabsf(n) + EPS);
                if (EMIT_HALF) out_h16[outIdx] = __float2half(h);
                else           __stcs(out_f32 + outIdx, h);
                outIdx += strideO;
            }
        } else {
#pragma unroll
            for (int j = 0; j < CH; j++) {
                const float zp = __half2float(buf[cur][j][0][ltid]) + bz + rz * h;
                const float ip = __half2float(buf[cur][j][1][ltid]) + bi + ri * h;
                const float fp = __half2float(buf[cur][j][2][ltid]) + bf + rf * h;
                const float op = __half2float(buf[cur][j][3][ltid]) + bo + ro * h;
                const float zt = fast_tanh(zp);
                const float ot = fast_sigmoid(op);
                const float fm = fp + m;
                const float mn = fmaxf(fm, ip);
                const float ft = __expf(fm - mn);
                const float it = __expf(ip - mn);
                c = ft * c + it * zt;
                n = ft * n + it;
                m = mn;
                h = ot * __fdividef(c, fabsf(n) + EPS);
                if (EMIT_HALF) out_h16[outIdx] = __float2half(h);
                else           __stcs(out_f32 + outIdx, h);
                outIdx += strideO;
            }
        }
        __syncthreads();   // all reads of buf[cur] done before refill

        if (k + 3 < NCH) {
            wait_mblock(vflags, k + 3); __threadfence();
            SCAN_PREFETCH(cur, k + 3);
        }
    }
#undef SCAN_PREFETCH

    hf[lbd + d] = h;
    extraf[lb3d + 0 * DIM + d] = c;
    extraf[lb3d + 1 * DIM + d] = n;
    extraf[lb3d + 2 * DIM + d] = m;
}

// ---------------------------------------------------------------------------
// Launch. Inputs: input, h0, extra0, W0, b0, r0, W1, b1, r1
// Output: output[S,B,D] || h_f[L,B,D] || extra_f[L,B,3D]
// ---------------------------------------------------------------------------
extern "C" void kernel_launch(void* const* d_in, const int* in_sizes, int n_in,
                              void* d_out, int out_size)
{
    const float* input  = (const float*)d_in[0];
    const float* h0     = (const float*)d_in[1];
    const float* extra0 = (const float*)d_in[2];
    const float* W0     = (const float*)d_in[3];
    const float* b0     = (const float*)d_in[4];
    const float* r0     = (const float*)d_in[5];
    const float* W1     = (const float*)d_in[6];
    const float* b1     = (const float*)d_in[7];
    const float* r1     = (const float*)d_in[8];

    float* out    = (float*)d_out;
    float* hf     = out + (size_t)S_LEN * BATCH * DIM;
    float* extraf = hf + (size_t)2 * BATCH * DIM;

    __half* pre;  cudaGetSymbolAddress((void**)&pre, g_pre);
    __half* ah;   cudaGetSymbolAddress((void**)&ah,  g_ah);
    __half* wh0;  cudaGetSymbolAddress((void**)&wh0, g_wh0);
    __half* wh1;  cudaGetSymbolAddress((void**)&wh1, g_wh1);
    int* flags;   cudaGetSymbolAddress((void**)&flags, g_flags);

    cudaFuncSetAttribute(fused_kernel<true>,
                         cudaFuncAttributeMaxDynamicSharedMemorySize, FUSED_SMEM);
    cudaFuncSetAttribute(fused_kernel<false>,
                         cudaFuncAttributeMaxDynamicSharedMemorySize, FUSED_SMEM);

    const int nA = MROWS * KDIM;   // 16.7M
    const int nW = GDIM * KDIM;    // 4.2M

    // Reset completion flags (graph-capturable async memset).
    cudaMemsetAsync(flags, 0, sizeof(int) * 2 * 128);

    // All converts up front
    convert_kernel<<<nA / 1024, 256>>>(input, ah, nA);
    convert_kernel<<<nW / 1024, 256>>>(W0, wh0, nW);
    convert_kernel<<<nW / 1024, 256>>>(W1, wh1, nW);

    dim3 grid(GEMM_CTAS + SCAN_CTAS);   // 4224; scan CTAs scheduled last

    // ---- Layer 0: GEMM0 + scan0 fused (scan writes fp16 h into ah) ----
    fused_kernel<true><<<grid, 128, FUSED_SMEM>>>(
        ah, wh0, pre, b0, r0, h0, extra0, 0,
        nullptr, ah, hf, extraf, flags);

    // ---- Layer 1: GEMM1 + scan1 fused (scan writes fp32 output) ----
    fused_kernel<false><<<grid, 128, FUSED_SMEM>>>(
        ah, wh1, pre, b1, r1, h0, extra0, 1,
        out, nullptr, hf, extraf, flags + 128);
}

// round 13
// speedup vs baseline: 1.0555x; 1.0555x over previous
#include <cuda_runtime.h>
#include <cuda_fp16.h>
#include <math.h>
#include <stdint.h>

// Problem constants (fixed: S=1024, B=16, I=D=1024, L=2)
#define S_LEN 1024
#define BATCH 16
#define DIM   1024
#define GDIM  (4 * DIM)       // 4096
#define KDIM  1024
#define MROWS (S_LEN * BATCH) // 16384
#define EPS 1e-6f

// ---------------------------------------------------------------------------
// Device scratch (no allocation allowed in kernel_launch)
// ---------------------------------------------------------------------------
__device__ __half g_pre[(size_t)S_LEN * BATCH * GDIM];  // 134 MB (NO bias; fp16)
__device__ __half g_ah[(size_t)MROWS * KDIM];           // 33.5 MB (A in fp16)
__device__ __half g_wh0[(size_t)GDIM * KDIM];           // 8.4 MB  (W0 fp16)
__device__ __half g_wh1[(size_t)GDIM * KDIM];           // 8.4 MB  (W1 fp16)

// ---------------------------------------------------------------------------
// PTX helpers — base-target only (NO tcgen05: harness emits compute_103 PTX)
// ---------------------------------------------------------------------------
__device__ __forceinline__ uint32_t smem_u32(const void* p) {
    uint32_t a;
    asm("{ .reg .u64 t; cvta.to.shared.u64 t, %1; cvt.u32.u64 %0, t; }"
        : "=r"(a) : "l"(p));
    return a;
}
__device__ __forceinline__ void cp16(uint32_t dst, const void* src) {
    asm volatile("cp.async.cg.shared.global [%0], [%1], 16;"
                 :: "r"(dst), "l"(src));
}
__device__ __forceinline__ void ldsm_x4(uint32_t& r0, uint32_t& r1,
                                        uint32_t& r2, uint32_t& r3,
                                        uint32_t addr) {
    asm volatile("ldmatrix.sync.aligned.m8n8.x4.shared.b16 {%0,%1,%2,%3}, [%4];"
                 : "=r"(r0), "=r"(r1), "=r"(r2), "=r"(r3) : "r"(addr));
}
__device__ __forceinline__ void mma_f16(float* d, const uint32_t* a,
                                        uint32_t b0, uint32_t b1) {
    asm volatile(
        "mma.sync.aligned.m16n8k16.row.col.f32.f16.f16.f32 "
        "{%0,%1,%2,%3}, {%4,%5,%6,%7}, {%8,%9}, {%0,%1,%2,%3};"
        : "+f"(d[0]), "+f"(d[1]), "+f"(d[2]), "+f"(d[3])
        : "r"(a[0]), "r"(a[1]), "r"(a[2]), "r"(a[3]), "r"(b0), "r"(b1));
}

// Fast math (rel err ~2^-21; far under the 1e-3 budget)
__device__ __forceinline__ float fast_sigmoid(float x) {
    return __fdividef(1.0f, 1.0f + __expf(-x));
}
__device__ __forceinline__ float fast_tanh(float x) {
    float e = __expf(2.0f * x);
    return __fdividef(e - 1.0f, e + 1.0f);
}

// Swizzle: rows are 64B (32 fp16); XOR the 16B-segment index with (row>>1)&3
__device__ __forceinline__ uint32_t swz_addr(uint32_t plane_base, int row, int seg) {
    return plane_base + (uint32_t)(row * 64) + ((uint32_t)((seg ^ ((row >> 1) & 3)) << 4));
}

// ---------------------------------------------------------------------------
// Fused fp32 -> fp16 convert: input (16384 blocks), W0 (4096), W1 (4096).
// ---------------------------------------------------------------------------
#define NA_BLOCKS (MROWS * KDIM / 1024)   // 16384
#define NW_BLOCKS (GDIM * KDIM / 1024)    // 4096

__global__ __launch_bounds__(256)
void convert_all_kernel(const float* __restrict__ input,
                        const float* __restrict__ W0,
                        const float* __restrict__ W1,
                        __half* __restrict__ ah,
                        __half* __restrict__ wh0,
                        __half* __restrict__ wh1)
{
    const float* src;
    __half* dst;
    int blk = blockIdx.x;
    if (blk < NA_BLOCKS)                { src = input; dst = ah; }
    else if (blk < NA_BLOCKS + NW_BLOCKS) { src = W0; dst = wh0; blk -= NA_BLOCKS; }
    else                                { src = W1; dst = wh1; blk -= NA_BLOCKS + NW_BLOCKS; }

    int i = (blk * 256 + threadIdx.x) * 4;
    float4 v = *reinterpret_cast<const float4*>(src + i);
    __half2* d2 = reinterpret_cast<__half2*>(dst + i);
    d2[0] = __half2(__float2half(v.x), __float2half(v.y));
    d2[1] = __half2(__float2half(v.z), __float2half(v.w));
}

// ---------------------------------------------------------------------------
// HMMA GEMM: C[M=16384, N=4096] = A[M,K=1024] @ W[N,K]^T   (fp16 in/out,
// fp32 accum, NO bias — scan adds it in fp32).
// R11 shape: CTA 128x128, 4 warps (2Mx2N, 64x64 warp tiles), 128-thr CTAs,
// 2 CTAs/SM (two independent barrier domains).
// R13: K-chunk 64 (two 32-sub-chunks/stage), 3 stages (96KB) — halves the
// wait_group+__syncthreads count (32 -> 16).
// ---------------------------------------------------------------------------
#define KCHUNK 64
#define NCHUNK (KDIM / KCHUNK)       // 16
#define PLANE  8192                  // 128 rows * 64 bytes (one 32-k sub-plane)
#define SUB_BYTES (2 * PLANE)        // [A, W] for one 32-k sub-chunk = 16 KB
#define STAGE_BYTES (2 * SUB_BYTES)  // 32 KB
#define STAGES 3
#define GEMM_SMEM (STAGES * STAGE_BYTES)   // 96 KB

__device__ __forceinline__ void load_chunk(uint32_t stage_base,
                                           const __half* Ap,
                                           const __half* Wp,
                                           int k0, int tid)
{
    // 2 subs x 2 planes x 128 rows x 4 segs = 2048 cp16 / 128 thr = 16 each.
#pragma unroll
    for (int sub = 0; sub < 2; sub++) {
#pragma unroll
        for (int p = 0; p < 2; p++) {
            const __half* src = (p == 0) ? Ap : Wp;
#pragma unroll
            for (int h = 0; h < 4; h++) {
                int it = tid + h * 128;          // 0..511
                int row = it >> 2;
                int seg = it & 3;
                cp16(swz_addr(stage_base + sub * SUB_BYTES + p * PLANE, row, seg),
                     src + (size_t)row * KDIM + k0 + sub * 32 + seg * 8);
            }
        }
    }
}

__global__ __launch_bounds__(128, 2)
void gemm_tc_kernel(const __half* __restrict__ Ah,
                    const __half* __restrict__ Wh,
                    __half* __restrict__ C)
{
    extern __shared__ __align__(1024) char smem[];
    const uint32_t sbase = smem_u32(smem);
    const int tid  = threadIdx.x;
    const int wid  = tid >> 5;      // 0..3
    const int lane = tid & 31;
    const int warp_m = wid & 1;     // 2 warps in M: 64 rows each
    const int warp_n = wid >> 1;    // 2 warps in N: 64 cols each
    const int bm = blockIdx.y * 128;
    const int bn = blockIdx.x * 128;

    const __half* Ap = Ah + (size_t)bm * KDIM;
    const __half* Wp = Wh + (size_t)bn * KDIM;

    float acc[4][8][4];
#pragma unroll
    for (int i = 0; i < 4; i++)
#pragma unroll
        for (int j = 0; j < 8; j++)
#pragma unroll
            for (int k = 0; k < 4; k++) acc[i][j][k] = 0.0f;

    // Prologue: stages 0,1
    load_chunk(sbase + 0 * STAGE_BYTES, Ap, Wp, 0 * KCHUNK, tid);
    asm volatile("cp.async.commit_group;");
    load_chunk(sbase + 1 * STAGE_BYTES, Ap, Wp, 1 * KCHUNK, tid);
    asm volatile("cp.async.commit_group;");

    const int a_lrow = lane & 15;
    const int a_lseg = lane >> 4;
    const int b_lrow = (lane & 7) + ((lane >> 4) << 3);
    const int b_lseg = (lane >> 3) & 1;

    for (int i = 0; i < NCHUNK; i++) {
        if (i + 1 < NCHUNK) { asm volatile("cp.async.wait_group 1;"); }
        else                { asm volatile("cp.async.wait_group 0;"); }
        __syncthreads();

        if (i + 2 < NCHUNK) {
            load_chunk(sbase + (uint32_t)((i + 2) % STAGES) * STAGE_BYTES,
                       Ap, Wp, (i + 2) * KCHUNK, tid);
            asm volatile("cp.async.commit_group;");
        }

        const uint32_t st = sbase + (uint32_t)(i % STAGES) * STAGE_BYTES;

#pragma unroll
        for (int sub = 0; sub < 2; sub++) {
            const uint32_t base_a = st + sub * SUB_BYTES;
            const uint32_t base_w = base_a + PLANE;
#pragma unroll
            for (int ks = 0; ks < 2; ks++) {
                uint32_t a[4][4], w[4][4];
#pragma unroll
                for (int jj = 0; jj < 4; jj++) {
                    int row = warp_n * 64 + jj * 16 + b_lrow;
                    ldsm_x4(w[jj][0], w[jj][1], w[jj][2], w[jj][3],
                            swz_addr(base_w, row, ks * 2 + b_lseg));
                }
#pragma unroll
                for (int ti = 0; ti < 4; ti++) {
                    int row = warp_m * 64 + ti * 16 + a_lrow;
                    ldsm_x4(a[ti][0], a[ti][1], a[ti][2], a[ti][3],
                            swz_addr(base_a, row, ks * 2 + a_lseg));
                }
#pragma unroll
                for (int ti = 0; ti < 4; ti++)
#pragma unroll
                    for (int jj = 0; jj < 4; jj++) {
                        mma_f16(acc[ti][2 * jj + 0], a[ti], w[jj][0], w[jj][1]);
                        mma_f16(acc[ti][2 * jj + 1], a[ti], w[jj][2], w[jj][3]);
                    }
            }
        }
    }

    // Epilogue: fp16 streaming stores (C read once by the scan; 134MB)
    const int mrow0 = bm + warp_m * 64 + (lane >> 2);
    const int col0  = bn + warp_n * 64 + (lane & 3) * 2;
#pragma unroll
    for (int ti = 0; ti < 4; ti++) {
        const int r0 = mrow0 + ti * 16;
#pragma unroll
        for (int g = 0; g < 8; g++) {
            int col = col0 + g * 8;
            __half2 v0 = __floats2half2_rn(acc[ti][g][0], acc[ti][g][1]);
            __half2 v1 = __floats2half2_rn(acc[ti][g][2], acc[ti][g][3]);
            __stcs(reinterpret_cast<__half2*>(C + (size_t)r0 * GDIM + col), v0);
            __stcs(reinterpret_cast<__half2*>(C + (size_t)(r0 + 8) * GDIM + col), v1);
        }
    }
}

// ---------------------------------------------------------------------------
// Elementwise sLSTM scan: fp16 pre (bias-free) staged via cp.async, triple
// buffered (3 x 16-step tiles = 24 KB). Bias added in fp32 here.
// EMIT_HALF: layer-0 writes h as fp16 (feeds GEMM1 A directly).
// ---------------------------------------------------------------------------
#define CH 16
#define NCH (S_LEN / CH)   // 64 chunks

template <bool EMIT_HALF>
__global__ __launch_bounds__(64)
void slstm_scan_kernel(const __half* __restrict__ pre,    // [S,B,4D] (no bias)
                       const float* __restrict__ bias,    // [4D]
                       const float* __restrict__ r,       // [4D]
                       const float* __restrict__ h0,      // [L,B,D]
                       const float* __restrict__ extra0,  // [L,B,3D]
                       int layer,
                       float* __restrict__ out_f32,       // [S,B,D] (or null)
                       __half* __restrict__ out_h16,      // [S,B,D] (or null)
                       float* __restrict__ hf,            // [L,B,D]
                       float* __restrict__ extraf)        // [L,B,3D]
{
    __shared__ __half buf[3][CH][4][64];   // 12 KB

    const int ltid = threadIdx.x;                 // 0..63
    const int L0 = blockIdx.x * 64;               // lane base (all same b)
    const int b  = L0 >> 10;
    const int d0 = L0 & (DIM - 1);
    const int d  = d0 + ltid;

    const float rz = r[0 * DIM + d];
    const float ri = r[1 * DIM + d];
    const float rf = r[2 * DIM + d];
    const float ro = r[3 * DIM + d];
    const float bz = bias[0 * DIM + d];
    const float bi = bias[1 * DIM + d];
    const float bf = bias[2 * DIM + d];
    const float bo = bias[3 * DIM + d];
    const bool rzero = (rz == 0.0f) && (ri == 0.0f) && (rf == 0.0f) && (ro == 0.0f);

    const size_t lbd  = (size_t)layer * BATCH * DIM + (size_t)b * DIM;
    const size_t lb3d = (size_t)layer * BATCH * 3 * DIM + (size_t)b * 3 * DIM;

    float h = h0[lbd + d];
    float c = extra0[lb3d + 0 * DIM + d];
    float n = extra0[lb3d + 1 * DIM + d];
    float m = extra0[lb3d + 2 * DIM + d];

    // Prefetch mapping: g = gate (0..3), cc = 16B chunk (0..7: lanes cc*8..+7),
    // sh = step parity. Each thread issues CH/2 cp16 per chunk.
    const int g  = ltid >> 4;
    const int cc = ltid & 7;
    const int sh = (ltid >> 3) & 1;
    const size_t strideT = (size_t)BATCH * GDIM;
    const __half* src0 = pre + (size_t)b * GDIM + (size_t)g * DIM + d0 + cc * 8;

#define SCAN_PREFETCH(stage, k)                                               \
    do {                                                                      \
        const __half* _s = src0 + ((size_t)(k) * CH + sh) * strideT;          \
        _Pragma("unroll")                                                     \
        for (int _jj = 0; _jj < CH / 2; _jj++) {                              \
            cp16(smem_u32(&buf[stage][2 * _jj + sh][g][cc * 8]), _s);         \
            _s += 2 * strideT;                                                \
        }                                                                     \
        asm volatile("cp.async.commit_group;");                               \
    } while (0)

    SCAN_PREFETCH(0, 0);
    SCAN_PREFETCH(1, 1);
    SCAN_PREFETCH(2, 2);

    size_t outIdx = (size_t)b * DIM + d;
    const size_t strideO = (size_t)BATCH * DIM;

    for (int k = 0; k < NCH; k++) {
        if (k + 2 < NCH)      { asm volatile("cp.async.wait_group 2;"); }
        else if (k + 1 < NCH) { asm volatile("cp.async.wait_group 1;"); }
        else                  { asm volatile("cp.async.wait_group 0;"); }
        __syncthreads();

        const int cur = k % 3;

        if (rzero) {
            float zt[CH], ot[CH];
#pragma unroll
            for (int j = 0; j < CH; j++) {
                zt[j] = fast_tanh(__half2float(buf[cur][j][0][ltid]) + bz);
                ot[j] = fast_sigmoid(__half2float(buf[cur][j][3][ltid]) + bo);
            }
#pragma unroll
            for (int j = 0; j < CH; j++) {
                const float ip = __half2float(buf[cur][j][1][ltid]) + bi;
                const float fm = __half2float(buf[cur][j][2][ltid]) + bf + m;
                const float mn = fmaxf(fm, ip);
                const float ft = __expf(fm - mn);
                const float it = __expf(ip - mn);
                c = ft * c + it * zt[j];
                n = ft * n + it;
                m = mn;
                h = ot[j] * __fdividef(c, fabsf(n) + EPS);
                if (EMIT_HALF) out_h16[outIdx] = __float2half(h);
                else           __stcs(out_f32 + outIdx, h);
                outIdx += strideO;
            }
        } else {
#pragma unroll
            for (int j = 0; j < CH; j++) {
                const float zp = __half2float(buf[cur][j][0][ltid]) + bz + rz * h;
                const float ip = __half2float(buf[cur][j][1][ltid]) + bi + ri * h;
                const float fp = __half2float(buf[cur][j][2][ltid]) + bf + rf * h;
                const float op = __half2float(buf[cur][j][3][ltid]) + bo + ro * h;
                const float zt = fast_tanh(zp);
                const float ot = fast_sigmoid(op);
                const float fm = fp + m;
                const float mn = fmaxf(fm, ip);
                const float ft = __expf(fm - mn);
                const float it = __expf(ip - mn);
                c = ft * c + it * zt;
                n = ft * n + it;
                m = mn;
                h = ot * __fdividef(c, fabsf(n) + EPS);
                if (EMIT_HALF) out_h16[outIdx] = __float2half(h);
                else           __stcs(out_f32 + outIdx, h);
                outIdx += strideO;
            }
        }
        __syncthreads();   // all reads of buf[cur] done before refill

        if (k + 3 < NCH) {
            SCAN_PREFETCH(cur, k + 3);
        }
    }
#undef SCAN_PREFETCH

    hf[lbd + d] = h;
    extraf[lb3d + 0 * DIM + d] = c;
    extraf[lb3d + 1 * DIM + d] = n;
    extraf[lb3d + 2 * DIM + d] = m;
}

// ---------------------------------------------------------------------------
// Launch. Inputs: input, h0, extra0, W0, b0, r0, W1, b1, r1
// Output: output[S,B,D] || h_f[L,B,D] || extra_f[L,B,3D]
// ---------------------------------------------------------------------------
extern "C" void kernel_launch(void* const* d_in, const int* in_sizes, int n_in,
                              void* d_out, int out_size)
{
    const float* input  = (const float*)d_in[0];
    const float* h0     = (const float*)d_in[1];
    const float* extra0 = (const float*)d_in[2];
    const float* W0     = (const float*)d_in[3];
    const float* b0     = (const float*)d_in[4];
    const float* r0     = (const float*)d_in[5];
    const float* W1     = (const float*)d_in[6];
    const float* b1     = (const float*)d_in[7];
    const float* r1     = (const float*)d_in[8];

    float* out    = (float*)d_out;
    float* hf     = out + (size_t)S_LEN * BATCH * DIM;
    float* extraf = hf + (size_t)2 * BATCH * DIM;

    __half* pre;  cudaGetSymbolAddress((void**)&pre, g_pre);
    __half* ah;   cudaGetSymbolAddress((void**)&ah,  g_ah);
    __half* wh0;  cudaGetSymbolAddress((void**)&wh0, g_wh0);
    __half* wh1;  cudaGetSymbolAddress((void**)&wh1, g_wh1);

    cudaFuncSetAttribute(gemm_tc_kernel,
                         cudaFuncAttributeMaxDynamicSharedMemorySize, GEMM_SMEM);

    dim3 gemmGrid(GDIM / 128, MROWS / 128);   // (32, 128) = 4096 CTAs
    dim3 scanGrid((BATCH * DIM) / 64);        // 256

    // All converts in ONE launch
    convert_all_kernel<<<NA_BLOCKS + 2 * NW_BLOCKS, 256>>>(
        input, W0, W1, ah, wh0, wh1);

    // ---- Layer 0 ----
    gemm_tc_kernel<<<gemmGrid, 128, GEMM_SMEM>>>(ah, wh0, pre);
    slstm_scan_kernel<true><<<scanGrid, 64>>>(pre, b0, r0, h0, extra0, 0,
                                              nullptr, ah, hf, extraf);

    // ---- Layer 1 ----
    gemm_tc_kernel<<<gemmGrid, 128, GEMM_SMEM>>>(ah, wh1, pre);
    slstm_scan_kernel<false><<<scanGrid, 64>>>(pre, b1, r1, h0, extra0, 1,
                                               out, nullptr, hf, extraf);
}

// round 14
// speedup vs baseline: 1.1972x; 1.1342x over previous
#include <cuda_runtime.h>
#include <cuda_fp16.h>
#include <math.h>
#include <stdint.h>

// Problem constants (fixed: S=1024, B=16, I=D=1024, L=2)
#define S_LEN 1024
#define BATCH 16
#define DIM   1024
#define GDIM  (4 * DIM)       // 4096
#define KDIM  1024
#define MROWS (S_LEN * BATCH) // 16384
#define EPS 1e-6f

// ---------------------------------------------------------------------------
// Device scratch (no allocation allowed in kernel_launch)
// ---------------------------------------------------------------------------
__device__ __half g_pre[(size_t)S_LEN * BATCH * GDIM];  // 134 MB (NO bias; fp16)
__device__ __half g_ah[(size_t)MROWS * KDIM];           // 33.5 MB (A in fp16)
__device__ __half g_wh0[(size_t)GDIM * KDIM];           // 8.4 MB  (W0 fp16)
__device__ __half g_wh1[(size_t)GDIM * KDIM];           // 8.4 MB  (W1 fp16)

// ---------------------------------------------------------------------------
// PTX helpers — base-target only (NO tcgen05: harness emits compute_103 PTX)
// ---------------------------------------------------------------------------
__device__ __forceinline__ uint32_t smem_u32(const void* p) {
    uint32_t a;
    asm("{ .reg .u64 t; cvta.to.shared.u64 t, %1; cvt.u32.u64 %0, t; }"
        : "=r"(a) : "l"(p));
    return a;
}
__device__ __forceinline__ void cp16(uint32_t dst, const void* src) {
    asm volatile("cp.async.cg.shared.global [%0], [%1], 16;"
                 :: "r"(dst), "l"(src));
}
__device__ __forceinline__ void ldsm_x4(uint32_t& r0, uint32_t& r1,
                                        uint32_t& r2, uint32_t& r3,
                                        uint32_t addr) {
    asm volatile("ldmatrix.sync.aligned.m8n8.x4.shared.b16 {%0,%1,%2,%3}, [%4];"
                 : "=r"(r0), "=r"(r1), "=r"(r2), "=r"(r3) : "r"(addr));
}
__device__ __forceinline__ void mma_f16(float* d, const uint32_t* a,
                                        uint32_t b0, uint32_t b1) {
    asm volatile(
        "mma.sync.aligned.m16n8k16.row.col.f32.f16.f16.f32 "
        "{%0,%1,%2,%3}, {%4,%5,%6,%7}, {%8,%9}, {%0,%1,%2,%3};"
        : "+f"(d[0]), "+f"(d[1]), "+f"(d[2]), "+f"(d[3])
        : "r"(a[0]), "r"(a[1]), "r"(a[2]), "r"(a[3]), "r"(b0), "r"(b1));
}

// Fast math (rel err ~2^-21; far under the 1e-3 budget)
__device__ __forceinline__ float fast_sigmoid(float x) {
    return __fdividef(1.0f, 1.0f + __expf(-x));
}
__device__ __forceinline__ float fast_tanh(float x) {
    float e = __expf(2.0f * x);
    return __fdividef(e - 1.0f, e + 1.0f);
}

// Swizzle: rows are 64B (32 fp16); XOR the 16B-segment index with (row>>1)&3
__device__ __forceinline__ uint32_t swz_addr(uint32_t plane_base, int row, int seg) {
    return plane_base + (uint32_t)(row * 64) + ((uint32_t)((seg ^ ((row >> 1) & 3)) << 4));
}

// ---------------------------------------------------------------------------
// Fused fp32 -> fp16 convert: input (16384 blocks), W0 (4096), W1 (4096).
// ---------------------------------------------------------------------------
#define NA_BLOCKS (MROWS * KDIM / 1024)   // 16384
#define NW_BLOCKS (GDIM * KDIM / 1024)    // 4096

__global__ __launch_bounds__(256)
void convert_all_kernel(const float* __restrict__ input,
                        const float* __restrict__ W0,
                        const float* __restrict__ W1,
                        __half* __restrict__ ah,
                        __half* __restrict__ wh0,
                        __half* __restrict__ wh1)
{
    const float* src;
    __half* dst;
    int blk = blockIdx.x;
    if (blk < NA_BLOCKS)                  { src = input; dst = ah; }
    else if (blk < NA_BLOCKS + NW_BLOCKS) { src = W0; dst = wh0; blk -= NA_BLOCKS; }
    else                                  { src = W1; dst = wh1; blk -= NA_BLOCKS + NW_BLOCKS; }

    int i = (blk * 256 + threadIdx.x) * 4;
    float4 v = __ldcs(reinterpret_cast<const float4*>(src + i));
    __half2* d2 = reinterpret_cast<__half2*>(dst + i);
    d2[0] = __half2(__float2half(v.x), __float2half(v.y));
    d2[1] = __half2(__float2half(v.z), __float2half(v.w));
}

// ---------------------------------------------------------------------------
// HMMA GEMM (exact R11 best config): C[M,N] = A @ W^T, fp16 in/out, fp32
// accum, NO bias. CTA 128x128, 4 warps (2Mx2N, 64x64 warp tiles), 128-thr
// CTAs, 2 CTAs/SM. K-chunk 32, 4-stage cp.async pipeline (16KB/stage).
// ---------------------------------------------------------------------------
#define KCHUNK 32
#define NCHUNK (KDIM / KCHUNK)       // 32
#define PLANE  8192                  // 128 rows * 64 bytes
#define STAGE_BYTES (2 * PLANE)      // [A, W] = 16 KB
#define STAGES 4
#define GEMM_SMEM (STAGES * STAGE_BYTES)   // 64 KB

__device__ __forceinline__ void load_chunk(uint32_t stage_base,
                                           const __half* Ap,
                                           const __half* Wp,
                                           int k0, int tid)
{
    // 2 planes x 128 rows x 4 segs(16B) = 1024 cp16 / 128 threads = 8 each.
#pragma unroll
    for (int p = 0; p < 2; p++) {
        const __half* src = (p == 0) ? Ap : Wp;
#pragma unroll
        for (int h = 0; h < 4; h++) {
            int it = tid + h * 128;          // 0..511
            int row = it >> 2;
            int seg = it & 3;
            cp16(swz_addr(stage_base + p * PLANE, row, seg),
                 src + (size_t)row * KDIM + k0 + seg * 8);
        }
    }
}

__global__ __launch_bounds__(128, 2)
void gemm_tc_kernel(const __half* __restrict__ Ah,
                    const __half* __restrict__ Wh,
                    __half* __restrict__ C)
{
    extern __shared__ __align__(1024) char smem[];
    const uint32_t sbase = smem_u32(smem);
    const int tid  = threadIdx.x;
    const int wid  = tid >> 5;      // 0..3
    const int lane = tid & 31;
    const int warp_m = wid & 1;     // 2 warps in M: 64 rows each
    const int warp_n = wid >> 1;    // 2 warps in N: 64 cols each
    const int bm = blockIdx.y * 128;
    const int bn = blockIdx.x * 128;

    const __half* Ap = Ah + (size_t)bm * KDIM;
    const __half* Wp = Wh + (size_t)bn * KDIM;

    float acc[4][8][4];
#pragma unroll
    for (int i = 0; i < 4; i++)
#pragma unroll
        for (int j = 0; j < 8; j++)
#pragma unroll
            for (int k = 0; k < 4; k++) acc[i][j][k] = 0.0f;

    // Prologue: stages 0,1,2
    load_chunk(sbase + 0 * STAGE_BYTES, Ap, Wp, 0 * KCHUNK, tid);
    asm volatile("cp.async.commit_group;");
    load_chunk(sbase + 1 * STAGE_BYTES, Ap, Wp, 1 * KCHUNK, tid);
    asm volatile("cp.async.commit_group;");
    load_chunk(sbase + 2 * STAGE_BYTES, Ap, Wp, 2 * KCHUNK, tid);
    asm volatile("cp.async.commit_group;");

    const int a_lrow = lane & 15;
    const int a_lseg = lane >> 4;
    const int b_lrow = (lane & 7) + ((lane >> 4) << 3);
    const int b_lseg = (lane >> 3) & 1;

    for (int i = 0; i < NCHUNK; i++) {
        const int rem = NCHUNK - 1 - i;
        if (rem >= 2)      { asm volatile("cp.async.wait_group 2;"); }
        else if (rem == 1) { asm volatile("cp.async.wait_group 1;"); }
        else               { asm volatile("cp.async.wait_group 0;"); }
        __syncthreads();

        if (i + 3 < NCHUNK) {
            load_chunk(sbase + (uint32_t)((i + 3) % STAGES) * STAGE_BYTES,
                       Ap, Wp, (i + 3) * KCHUNK, tid);
            asm volatile("cp.async.commit_group;");
        }

        const uint32_t st = sbase + (uint32_t)(i % STAGES) * STAGE_BYTES;
        const uint32_t base_a = st;
        const uint32_t base_w = st + PLANE;

#pragma unroll
        for (int ks = 0; ks < 2; ks++) {
            uint32_t a[4][4], w[4][4];
#pragma unroll
            for (int jj = 0; jj < 4; jj++) {
                int row = warp_n * 64 + jj * 16 + b_lrow;
                ldsm_x4(w[jj][0], w[jj][1], w[jj][2], w[jj][3],
                        swz_addr(base_w, row, ks * 2 + b_lseg));
            }
#pragma unroll
            for (int ti = 0; ti < 4; ti++) {
                int row = warp_m * 64 + ti * 16 + a_lrow;
                ldsm_x4(a[ti][0], a[ti][1], a[ti][2], a[ti][3],
                        swz_addr(base_a, row, ks * 2 + a_lseg));
            }
#pragma unroll
            for (int ti = 0; ti < 4; ti++)
#pragma unroll
                for (int jj = 0; jj < 4; jj++) {
                    mma_f16(acc[ti][2 * jj + 0], a[ti], w[jj][0], w[jj][1]);
                    mma_f16(acc[ti][2 * jj + 1], a[ti], w[jj][2], w[jj][3]);
                }
        }
    }

    // Epilogue: fp16 streaming stores (C read once by the scan; 134MB)
    const int mrow0 = bm + warp_m * 64 + (lane >> 2);
    const int col0  = bn + warp_n * 64 + (lane & 3) * 2;
#pragma unroll
    for (int ti = 0; ti < 4; ti++) {
        const int r0 = mrow0 + ti * 16;
#pragma unroll
        for (int g = 0; g < 8; g++) {
            int col = col0 + g * 8;
            __half2 v0 = __floats2half2_rn(acc[ti][g][0], acc[ti][g][1]);
            __half2 v1 = __floats2half2_rn(acc[ti][g][2], acc[ti][g][3]);
            __stcs(reinterpret_cast<__half2*>(C + (size_t)r0 * GDIM + col), v0);
            __stcs(reinterpret_cast<__half2*>(C + (size_t)(r0 + 8) * GDIM + col), v1);
        }
    }
}

// ---------------------------------------------------------------------------
// Elementwise sLSTM scan: fp16 pre (bias-free) staged via cp.async,
// QUAD buffered (4 x 16-step tiles = 16 KB; lookahead 3 chunks in flight).
// Bias added in fp32 here. EMIT_HALF: layer-0 writes h as fp16 into ah.
// ---------------------------------------------------------------------------
#define CH 16
#define NCH (S_LEN / CH)   // 64 chunks
#define SBUF 4

template <bool EMIT_HALF>
__global__ __launch_bounds__(64)
void slstm_scan_kernel(const __half* __restrict__ pre,    // [S,B,4D] (no bias)
                       const float* __restrict__ bias,    // [4D]
                       const float* __restrict__ r,       // [4D]
                       const float* __restrict__ h0,      // [L,B,D]
                       const float* __restrict__ extra0,  // [L,B,3D]
                       int layer,
                       float* __restrict__ out_f32,       // [S,B,D] (or null)
                       __half* __restrict__ out_h16,      // [S,B,D] (or null)
                       float* __restrict__ hf,            // [L,B,D]
                       float* __restrict__ extraf)        // [L,B,3D]
{
    __shared__ __half buf[SBUF][CH][4][64];   // 16 KB

    const int ltid = threadIdx.x;                 // 0..63
    const int L0 = blockIdx.x * 64;               // lane base (all same b)
    const int b  = L0 >> 10;
    const int d0 = L0 & (DIM - 1);
    const int d  = d0 + ltid;

    const float rz = r[0 * DIM + d];
    const float ri = r[1 * DIM + d];
    const float rf = r[2 * DIM + d];
    const float ro = r[3 * DIM + d];
    const float bz = bias[0 * DIM + d];
    const float bi = bias[1 * DIM + d];
    const float bf = bias[2 * DIM + d];
    const float bo = bias[3 * DIM + d];
    const bool rzero = (rz == 0.0f) && (ri == 0.0f) && (rf == 0.0f) && (ro == 0.0f);

    const size_t lbd  = (size_t)layer * BATCH * DIM + (size_t)b * DIM;
    const size_t lb3d = (size_t)layer * BATCH * 3 * DIM + (size_t)b * 3 * DIM;

    float h = h0[lbd + d];
    float c = extra0[lb3d + 0 * DIM + d];
    float n = extra0[lb3d + 1 * DIM + d];
    float m = extra0[lb3d + 2 * DIM + d];

    // Prefetch mapping: g = gate (0..3), cc = 16B chunk (0..7: lanes cc*8..+7),
    // sh = step parity. Each thread issues CH/2 cp16 per chunk.
    const int g  = ltid >> 4;
    const int cc = ltid & 7;
    const int sh = (ltid >> 3) & 1;
    const size_t strideT = (size_t)BATCH * GDIM;
    const __half* src0 = pre + (size_t)b * GDIM + (size_t)g * DIM + d0 + cc * 8;

#define SCAN_PREFETCH(stage, k)                                               \
    do {                                                                      \
        const __half* _s = src0 + ((size_t)(k) * CH + sh) * strideT;          \
        _Pragma("unroll")                                                     \
        for (int _jj = 0; _jj < CH / 2; _jj++) {                              \
            cp16(smem_u32(&buf[stage][2 * _jj + sh][g][cc * 8]), _s);         \
            _s += 2 * strideT;                                                \
        }                                                                     \
        asm volatile("cp.async.commit_group;");                               \
    } while (0)

    SCAN_PREFETCH(0, 0);
    SCAN_PREFETCH(1, 1);
    SCAN_PREFETCH(2, 2);
    SCAN_PREFETCH(3, 3);

    size_t outIdx = (size_t)b * DIM + d;
    const size_t strideO = (size_t)BATCH * DIM;

    for (int k = 0; k < NCH; k++) {
        if (k + 3 < NCH)      { asm volatile("cp.async.wait_group 3;"); }
        else if (k + 2 < NCH) { asm volatile("cp.async.wait_group 2;"); }
        else if (k + 1 < NCH) { asm volatile("cp.async.wait_group 1;"); }
        else                  { asm volatile("cp.async.wait_group 0;"); }
        __syncthreads();

        const int cur = k % SBUF;

        if (rzero) {
            float zt[CH], ot[CH];
#pragma unroll
            for (int j = 0; j < CH; j++) {
                zt[j] = fast_tanh(__half2float(buf[cur][j][0][ltid]) + bz);
                ot[j] = fast_sigmoid(__half2float(buf[cur][j][3][ltid]) + bo);
            }
#pragma unroll
            for (int j = 0; j < CH; j++) {
                const float ip = __half2float(buf[cur][j][1][ltid]) + bi;
                const float fm = __half2float(buf[cur][j][2][ltid]) + bf + m;
                const float mn = fmaxf(fm, ip);
                const float ft = __expf(fm - mn);
                const float it = __expf(ip - mn);
                c = ft * c + it * zt[j];
                n = ft * n + it;
                m = mn;
                h = ot[j] * __fdividef(c, fabsf(n) + EPS);
                if (EMIT_HALF) out_h16[outIdx] = __float2half(h);
                else           __stcs(out_f32 + outIdx, h);
                outIdx += strideO;
            }
        } else {
#pragma unroll
            for (int j = 0; j < CH; j++) {
                const float zp = __half2float(buf[cur][j][0][ltid]) + bz + rz * h;
                const float ip = __half2float(buf[cur][j][1][ltid]) + bi + ri * h;
                const float fp = __half2float(buf[cur][j][2][ltid]) + bf + rf * h;
                const float op = __half2float(buf[cur][j][3][ltid]) + bo + ro * h;
                const float zt = fast_tanh(zp);
                const float ot = fast_sigmoid(op);
                const float fm = fp + m;
                const float mn = fmaxf(fm, ip);
                const float ft = __expf(fm - mn);
                const float it = __expf(ip - mn);
                c = ft * c + it * zt;
                n = ft * n + it;
                m = mn;
                h = ot * __fdividef(c, fabsf(n) + EPS);
                if (EMIT_HALF) out_h16[outIdx] = __float2half(h);
                else           __stcs(out_f32 + outIdx, h);
                outIdx += strideO;
            }
        }
        __syncthreads();   // all reads of buf[cur] done before refill

        if (k + SBUF < NCH) {
            SCAN_PREFETCH(cur, k + SBUF);
        }
    }
#undef SCAN_PREFETCH

    hf[lbd + d] = h;
    extraf[lb3d + 0 * DIM + d] = c;
    extraf[lb3d + 1 * DIM + d] = n;
    extraf[lb3d + 2 * DIM + d] = m;
}

// ---------------------------------------------------------------------------
// Launch. Inputs: input, h0, extra0, W0, b0, r0, W1, b1, r1
// Output: output[S,B,D] || h_f[L,B,D] || extra_f[L,B,3D]
// ---------------------------------------------------------------------------
extern "C" void kernel_launch(void* const* d_in, const int* in_sizes, int n_in,
                              void* d_out, int out_size)
{
    const float* input  = (const float*)d_in[0];
    const float* h0     = (const float*)d_in[1];
    const float* extra0 = (const float*)d_in[2];
    const float* W0     = (const float*)d_in[3];
    const float* b0     = (const float*)d_in[4];
    const float* r0     = (const float*)d_in[5];
    const float* W1     = (const float*)d_in[6];
    const float* b1     = (const float*)d_in[7];
    const float* r1     = (const float*)d_in[8];

    float* out    = (float*)d_out;
    float* hf     = out + (size_t)S_LEN * BATCH * DIM;
    float* extraf = hf + (size_t)2 * BATCH * DIM;

    __half* pre;  cudaGetSymbolAddress((void**)&pre, g_pre);
    __half* ah;   cudaGetSymbolAddress((void**)&ah,  g_ah);
    __half* wh0;  cudaGetSymbolAddress((void**)&wh0, g_wh0);
    __half* wh1;  cudaGetSymbolAddress((void**)&wh1, g_wh1);

    cudaFuncSetAttribute(gemm_tc_kernel,
                         cudaFuncAttributeMaxDynamicSharedMemorySize, GEMM_SMEM);

    dim3 gemmGrid(GDIM / 128, MROWS / 128);   // (32, 128) = 4096 CTAs
    dim3 scanGrid((BATCH * DIM) / 64);        // 256

    // All converts in ONE launch
    convert_all_kernel<<<NA_BLOCKS + 2 * NW_BLOCKS, 256>>>(
        input, W0, W1, ah, wh0, wh1);

    // ---- Layer 0 ----
    gemm_tc_kernel<<<gemmGrid, 128, GEMM_SMEM>>>(ah, wh0, pre);
    slstm_scan_kernel<true><<<scanGrid, 64>>>(pre, b0, r0, h0, extra0, 0,
                                              nullptr, ah, hf, extraf);

    // ---- Layer 1 ----
    gemm_tc_kernel<<<gemmGrid, 128, GEMM_SMEM>>>(ah, wh1, pre);
    slstm_scan_kernel<false><<<scanGrid, 64>>>(pre, b1, r1, h0, extra0, 1,
                                               out, nullptr, hf, extraf);
}

// round 15
// speedup vs baseline: 1.2067x; 1.0080x over previous
#include <cuda_runtime.h>
#include <cuda_fp16.h>
#include <math.h>
#include <stdint.h>

// Problem constants (fixed: S=1024, B=16, I=D=1024, L=2)
#define S_LEN 1024
#define BATCH 16
#define DIM   1024
#define GDIM  (4 * DIM)       // 4096
#define KDIM  1024
#define MROWS (S_LEN * BATCH) // 16384
#define EPS 1e-6f

// ---------------------------------------------------------------------------
// Device scratch (no allocation allowed in kernel_launch)
// ---------------------------------------------------------------------------
__device__ __half g_pre[(size_t)S_LEN * BATCH * GDIM];  // 134 MB (NO bias; fp16)
__device__ __half g_ah[(size_t)MROWS * KDIM];           // 33.5 MB (A in fp16)
__device__ __half g_wh0[(size_t)GDIM * KDIM];           // 8.4 MB  (W0 fp16)
__device__ __half g_wh1[(size_t)GDIM * KDIM];           // 8.4 MB  (W1 fp16)

// ---------------------------------------------------------------------------
// PTX helpers — base-target only (NO tcgen05: harness emits compute_103 PTX)
// ---------------------------------------------------------------------------
__device__ __forceinline__ uint32_t smem_u32(const void* p) {
    uint32_t a;
    asm("{ .reg .u64 t; cvta.to.shared.u64 t, %1; cvt.u32.u64 %0, t; }"
        : "=r"(a) : "l"(p));
    return a;
}
__device__ __forceinline__ void cp16(uint32_t dst, const void* src) {
    asm volatile("cp.async.cg.shared.global [%0], [%1], 16;"
                 :: "r"(dst), "l"(src));
}
__device__ __forceinline__ void ldsm_x4(uint32_t& r0, uint32_t& r1,
                                        uint32_t& r2, uint32_t& r3,
                                        uint32_t addr) {
    asm volatile("ldmatrix.sync.aligned.m8n8.x4.shared.b16 {%0,%1,%2,%3}, [%4];"
                 : "=r"(r0), "=r"(r1), "=r"(r2), "=r"(r3) : "r"(addr));
}
__device__ __forceinline__ void mma_f16(float* d, const uint32_t* a,
                                        uint32_t b0, uint32_t b1) {
    asm volatile(
        "mma.sync.aligned.m16n8k16.row.col.f32.f16.f16.f32 "
        "{%0,%1,%2,%3}, {%4,%5,%6,%7}, {%8,%9}, {%0,%1,%2,%3};"
        : "+f"(d[0]), "+f"(d[1]), "+f"(d[2]), "+f"(d[3])
        : "r"(a[0]), "r"(a[1]), "r"(a[2]), "r"(a[3]), "r"(b0), "r"(b1));
}

// Fast math (rel err ~2^-21; far under the 1e-3 budget)
__device__ __forceinline__ float fast_tanh(float x) {
    float e = __expf(2.0f * x);
    return __fdividef(e - 1.0f, e + 1.0f);
}

// Swizzle: rows are 64B (32 fp16); XOR the 16B-segment index with (row>>1)&3
__device__ __forceinline__ uint32_t swz_addr(uint32_t plane_base, int row, int seg) {
    return plane_base + (uint32_t)(row * 64) + ((uint32_t)((seg ^ ((row >> 1) & 3)) << 4));
}

// ---------------------------------------------------------------------------
// Fused fp32 -> fp16 convert: input (16384 blocks), W0 (4096), W1 (4096).
// ---------------------------------------------------------------------------
#define NA_BLOCKS (MROWS * KDIM / 1024)   // 16384
#define NW_BLOCKS (GDIM * KDIM / 1024)    // 4096

__global__ __launch_bounds__(256)
void convert_all_kernel(const float* __restrict__ input,
                        const float* __restrict__ W0,
                        const float* __restrict__ W1,
                        __half* __restrict__ ah,
                        __half* __restrict__ wh0,
                        __half* __restrict__ wh1)
{
    const float* src;
    __half* dst;
    int blk = blockIdx.x;
    if (blk < NA_BLOCKS)                  { src = input; dst = ah; }
    else if (blk < NA_BLOCKS + NW_BLOCKS) { src = W0; dst = wh0; blk -= NA_BLOCKS; }
    else                                  { src = W1; dst = wh1; blk -= NA_BLOCKS + NW_BLOCKS; }

    int i = (blk * 256 + threadIdx.x) * 4;
    float4 v = __ldcs(reinterpret_cast<const float4*>(src + i));
    __half2* d2 = reinterpret_cast<__half2*>(dst + i);
    d2[0] = __half2(__float2half(v.x), __float2half(v.y));
    d2[1] = __half2(__float2half(v.z), __float2half(v.w));
}

// ---------------------------------------------------------------------------
// HMMA GEMM (R11/R14 best config — DO NOT PERTURB): C[M,N] = A @ W^T, fp16
// in/out, fp32 accum, NO bias. CTA 128x128, 4 warps (2Mx2N, 64x64 warp
// tiles), 128-thr CTAs, 2 CTAs/SM. K-chunk 32, 4-stage cp.async pipeline.
// ---------------------------------------------------------------------------
#define KCHUNK 32
#define NCHUNK (KDIM / KCHUNK)       // 32
#define PLANE  8192                  // 128 rows * 64 bytes
#define STAGE_BYTES (2 * PLANE)      // [A, W] = 16 KB
#define STAGES 4
#define GEMM_SMEM (STAGES * STAGE_BYTES)   // 64 KB

__device__ __forceinline__ void load_chunk(uint32_t stage_base,
                                           const __half* Ap,
                                           const __half* Wp,
                                           int k0, int tid)
{
    // 2 planes x 128 rows x 4 segs(16B) = 1024 cp16 / 128 threads = 8 each.
#pragma unroll
    for (int p = 0; p < 2; p++) {
        const __half* src = (p == 0) ? Ap : Wp;
#pragma unroll
        for (int h = 0; h < 4; h++) {
            int it = tid + h * 128;          // 0..511
            int row = it >> 2;
            int seg = it & 3;
            cp16(swz_addr(stage_base + p * PLANE, row, seg),
                 src + (size_t)row * KDIM + k0 + seg * 8);
        }
    }
}

__global__ __launch_bounds__(128, 2)
void gemm_tc_kernel(const __half* __restrict__ Ah,
                    const __half* __restrict__ Wh,
                    __half* __restrict__ C)
{
    extern __shared__ __align__(1024) char smem[];
    const uint32_t sbase = smem_u32(smem);
    const int tid  = threadIdx.x;
    const int wid  = tid >> 5;      // 0..3
    const int lane = tid & 31;
    const int warp_m = wid & 1;     // 2 warps in M: 64 rows each
    const int warp_n = wid >> 1;    // 2 warps in N: 64 cols each
    const int bm = blockIdx.y * 128;
    const int bn = blockIdx.x * 128;

    const __half* Ap = Ah + (size_t)bm * KDIM;
    const __half* Wp = Wh + (size_t)bn * KDIM;

    float acc[4][8][4];
#pragma unroll
    for (int i = 0; i < 4; i++)
#pragma unroll
        for (int j = 0; j < 8; j++)
#pragma unroll
            for (int k = 0; k < 4; k++) acc[i][j][k] = 0.0f;

    // Prologue: stages 0,1,2
    load_chunk(sbase + 0 * STAGE_BYTES, Ap, Wp, 0 * KCHUNK, tid);
    asm volatile("cp.async.commit_group;");
    load_chunk(sbase + 1 * STAGE_BYTES, Ap, Wp, 1 * KCHUNK, tid);
    asm volatile("cp.async.commit_group;");
    load_chunk(sbase + 2 * STAGE_BYTES, Ap, Wp, 2 * KCHUNK, tid);
    asm volatile("cp.async.commit_group;");

    const int a_lrow = lane & 15;
    const int a_lseg = lane >> 4;
    const int b_lrow = (lane & 7) + ((lane >> 4) << 3);
    const int b_lseg = (lane >> 3) & 1;

    for (int i = 0; i < NCHUNK; i++) {
        const int rem = NCHUNK - 1 - i;
        if (rem >= 2)      { asm volatile("cp.async.wait_group 2;"); }
        else if (rem == 1) { asm volatile("cp.async.wait_group 1;"); }
        else               { asm volatile("cp.async.wait_group 0;"); }
        __syncthreads();

        if (i + 3 < NCHUNK) {
            load_chunk(sbase + (uint32_t)((i + 3) % STAGES) * STAGE_BYTES,
                       Ap, Wp, (i + 3) * KCHUNK, tid);
            asm volatile("cp.async.commit_group;");
        }

        const uint32_t st = sbase + (uint32_t)(i % STAGES) * STAGE_BYTES;
        const uint32_t base_a = st;
        const uint32_t base_w = st + PLANE;

#pragma unroll
        for (int ks = 0; ks < 2; ks++) {
            uint32_t a[4][4], w[4][4];
#pragma unroll
            for (int jj = 0; jj < 4; jj++) {
                int row = warp_n * 64 + jj * 16 + b_lrow;
                ldsm_x4(w[jj][0], w[jj][1], w[jj][2], w[jj][3],
                        swz_addr(base_w, row, ks * 2 + b_lseg));
            }
#pragma unroll
            for (int ti = 0; ti < 4; ti++) {
                int row = warp_m * 64 + ti * 16 + a_lrow;
                ldsm_x4(a[ti][0], a[ti][1], a[ti][2], a[ti][3],
                        swz_addr(base_a, row, ks * 2 + a_lseg));
            }
#pragma unroll
            for (int ti = 0; ti < 4; ti++)
#pragma unroll
                for (int jj = 0; jj < 4; jj++) {
                    mma_f16(acc[ti][2 * jj + 0], a[ti], w[jj][0], w[jj][1]);
                    mma_f16(acc[ti][2 * jj + 1], a[ti], w[jj][2], w[jj][3]);
                }
        }
    }

    // Epilogue: fp16 streaming stores (C read once by the scan; 134MB)
    const int mrow0 = bm + warp_m * 64 + (lane >> 2);
    const int col0  = bn + warp_n * 64 + (lane & 3) * 2;
#pragma unroll
    for (int ti = 0; ti < 4; ti++) {
        const int r0 = mrow0 + ti * 16;
#pragma unroll
        for (int g = 0; g < 8; g++) {
            int col = col0 + g * 8;
            __half2 v0 = __floats2half2_rn(acc[ti][g][0], acc[ti][g][1]);
            __half2 v1 = __floats2half2_rn(acc[ti][g][2], acc[ti][g][3]);
            __stcs(reinterpret_cast<__half2*>(C + (size_t)r0 * GDIM + col), v0);
            __stcs(reinterpret_cast<__half2*>(C + (size_t)(r0 + 8) * GDIM + col), v1);
        }
    }
}

// ---------------------------------------------------------------------------
// Elementwise sLSTM scan: fp16 pre (bias-free) staged via cp.async,
// quad buffered. Bias added in fp32 here.
// R15: MUFU reduction — (a) one of exp(fm-mn)/exp(ip-mn) is always exp(0)=1,
// so compute e = exp(min-max) once and select; (b) fuse sigmoid and the
// c/(|n|+eps) divide into one __fdividef: h = c / ((1+e^{-op})(|n|+eps)).
// EMIT_HALF: layer-0 writes h as fp16 into ah (GEMM1's A operand).
// ---------------------------------------------------------------------------
#define CH 16
#define NCH (S_LEN / CH)   // 64 chunks
#define SBUF 4

template <bool EMIT_HALF>
__global__ __launch_bounds__(64)
void slstm_scan_kernel(const __half* __restrict__ pre,    // [S,B,4D] (no bias)
                       const float* __restrict__ bias,    // [4D]
                       const float* __restrict__ r,       // [4D]
                       const float* __restrict__ h0,      // [L,B,D]
                       const float* __restrict__ extra0,  // [L,B,3D]
                       int layer,
                       float* __restrict__ out_f32,       // [S,B,D] (or null)
                       __half* __restrict__ out_h16,      // [S,B,D] (or null)
                       float* __restrict__ hf,            // [L,B,D]
                       float* __restrict__ extraf)        // [L,B,3D]
{
    __shared__ __half buf[SBUF][CH][4][64];   // 16 KB

    const int ltid = threadIdx.x;                 // 0..63
    const int L0 = blockIdx.x * 64;               // lane base (all same b)
    const int b  = L0 >> 10;
    const int d0 = L0 & (DIM - 1);
    const int d  = d0 + ltid;

    const float rz = r[0 * DIM + d];
    const float ri = r[1 * DIM + d];
    const float rf = r[2 * DIM + d];
    const float ro = r[3 * DIM + d];
    const float bz = bias[0 * DIM + d];
    const float bi = bias[1 * DIM + d];
    const float bf = bias[2 * DIM + d];
    const float bo = bias[3 * DIM + d];
    const bool rzero = (rz == 0.0f) && (ri == 0.0f) && (rf == 0.0f) && (ro == 0.0f);

    const size_t lbd  = (size_t)layer * BATCH * DIM + (size_t)b * DIM;
    const size_t lb3d = (size_t)layer * BATCH * 3 * DIM + (size_t)b * 3 * DIM;

    float h = h0[lbd + d];
    float c = extra0[lb3d + 0 * DIM + d];
    float n = extra0[lb3d + 1 * DIM + d];
    float m = extra0[lb3d + 2 * DIM + d];

    // Prefetch mapping: g = gate (0..3), cc = 16B chunk (0..7: lanes cc*8..+7),
    // sh = step parity. Each thread issues CH/2 cp16 per chunk.
    const int g  = ltid >> 4;
    const int cc = ltid & 7;
    const int sh = (ltid >> 3) & 1;
    const size_t strideT = (size_t)BATCH * GDIM;
    const __half* src0 = pre + (size_t)b * GDIM + (size_t)g * DIM + d0 + cc * 8;

#define SCAN_PREFETCH(stage, k)                                               \
    do {                                                                      \
        const __half* _s = src0 + ((size_t)(k) * CH + sh) * strideT;          \
        _Pragma("unroll")                                                     \
        for (int _jj = 0; _jj < CH / 2; _jj++) {                              \
            cp16(smem_u32(&buf[stage][2 * _jj + sh][g][cc * 8]), _s);         \
            _s += 2 * strideT;                                                \
        }                                                                     \
        asm volatile("cp.async.commit_group;");                               \
    } while (0)

    SCAN_PREFETCH(0, 0);
    SCAN_PREFETCH(1, 1);
    SCAN_PREFETCH(2, 2);
    SCAN_PREFETCH(3, 3);

    size_t outIdx = (size_t)b * DIM + d;
    const size_t strideO = (size_t)BATCH * DIM;

    for (int k = 0; k < NCH; k++) {
        if (k + 3 < NCH)      { asm volatile("cp.async.wait_group 3;"); }
        else if (k + 2 < NCH) { asm volatile("cp.async.wait_group 2;"); }
        else if (k + 1 < NCH) { asm volatile("cp.async.wait_group 1;"); }
        else                  { asm volatile("cp.async.wait_group 0;"); }
        __syncthreads();

        const int cur = k % SBUF;

        if (rzero) {
            // Batch phase (full ILP): zt = tanh(z_pre), den = 1 + exp(-o_pre).
            float zt[CH], den[CH];
#pragma unroll
            for (int j = 0; j < CH; j++) {
                zt[j]  = fast_tanh(__half2float(buf[cur][j][0][ltid]) + bz);
                den[j] = 1.0f + __expf(-(__half2float(buf[cur][j][3][ltid]) + bo));
            }
            // Serial phase: 2 MUFU/step (exp-min + fused divide).
#pragma unroll
            for (int j = 0; j < CH; j++) {
                const float ip = __half2float(buf[cur][j][1][ltid]) + bi;
                const float fm = __half2float(buf[cur][j][2][ltid]) + bf + m;
                const float mn = fmaxf(fm, ip);
                const float e  = __expf(fminf(fm, ip) - mn);
                const bool ffl = fm >= ip;
                const float ft = ffl ? 1.0f : e;
                const float it = ffl ? e : 1.0f;
                c = ft * c + it * zt[j];
                n = ft * n + it;
                m = mn;
                h = __fdividef(c, den[j] * (fabsf(n) + EPS));
                if (EMIT_HALF) out_h16[outIdx] = __float2half(h);
                else           __stcs(out_f32 + outIdx, h);
                outIdx += strideO;
            }
        } else {
#pragma unroll
            for (int j = 0; j < CH; j++) {
                const float zp = __half2float(buf[cur][j][0][ltid]) + bz + rz * h;
                const float ip = __half2float(buf[cur][j][1][ltid]) + bi + ri * h;
                const float fp = __half2float(buf[cur][j][2][ltid]) + bf + rf * h;
                const float op = __half2float(buf[cur][j][3][ltid]) + bo + ro * h;
                const float zt  = fast_tanh(zp);
                const float den = 1.0f + __expf(-op);
                const float fm = fp + m;
                const float mn = fmaxf(fm, ip);
                const float e  = __expf(fminf(fm, ip) - mn);
                const bool ffl = fm >= ip;
                const float ft = ffl ? 1.0f : e;
                const float it = ffl ? e : 1.0f;
                c = ft * c + it * zt;
                n = ft * n + it;
                m = mn;
                h = __fdividef(c, den * (fabsf(n) + EPS));
                if (EMIT_HALF) out_h16[outIdx] = __float2half(h);
                else           __stcs(out_f32 + outIdx, h);
                outIdx += strideO;
            }
        }
        __syncthreads();   // all reads of buf[cur] done before refill

        if (k + SBUF < NCH) {
            SCAN_PREFETCH(cur, k + SBUF);
        }
    }
#undef SCAN_PREFETCH

    hf[lbd + d] = h;
    extraf[lb3d + 0 * DIM + d] = c;
    extraf[lb3d + 1 * DIM + d] = n;
    extraf[lb3d + 2 * DIM + d] = m;
}

// ---------------------------------------------------------------------------
// Launch. Inputs: input, h0, extra0, W0, b0, r0, W1, b1, r1
// Output: output[S,B,D] || h_f[L,B,D] || extra_f[L,B,3D]
// ---------------------------------------------------------------------------
extern "C" void kernel_launch(void* const* d_in, const int* in_sizes, int n_in,
                              void* d_out, int out_size)
{
    const float* input  = (const float*)d_in[0];
    const float* h0     = (const float*)d_in[1];
    const float* extra0 = (const float*)d_in[2];
    const float* W0     = (const float*)d_in[3];
    const float* b0     = (const float*)d_in[4];
    const float* r0     = (const float*)d_in[5];
    const float* W1     = (const float*)d_in[6];
    const float* b1     = (const float*)d_in[7];
    const float* r1     = (const float*)d_in[8];

    float* out    = (float*)d_out;
    float* hf     = out + (size_t)S_LEN * BATCH * DIM;
    float* extraf = hf + (size_t)2 * BATCH * DIM;

    __half* pre;  cudaGetSymbolAddress((void**)&pre, g_pre);
    __half* ah;   cudaGetSymbolAddress((void**)&ah,  g_ah);
    __half* wh0;  cudaGetSymbolAddress((void**)&wh0, g_wh0);
    __half* wh1;  cudaGetSymbolAddress((void**)&wh1, g_wh1);

    cudaFuncSetAttribute(gemm_tc_kernel,
                         cudaFuncAttributeMaxDynamicSharedMemorySize, GEMM_SMEM);

    dim3 gemmGrid(GDIM / 128, MROWS / 128);   // (32, 128) = 4096 CTAs
    dim3 scanGrid((BATCH * DIM) / 64);        // 256

    // All converts in ONE launch
    convert_all_kernel<<<NA_BLOCKS + 2 * NW_BLOCKS, 256>>>(
        input, W0, W1, ah, wh0, wh1);

    // ---- Layer 0 ----
    gemm_tc_kernel<<<gemmGrid, 128, GEMM_SMEM>>>(ah, wh0, pre);
    slstm_scan_kernel<true><<<scanGrid, 64>>>(pre, b0, r0, h0, extra0, 0,
                                              nullptr, ah, hf, extraf);

    // ---- Layer 1 ----
    gemm_tc_kernel<<<gemmGrid, 128, GEMM_SMEM>>>(ah, wh1, pre);
    slstm_scan_kernel<false><<<scanGrid, 64>>>(pre, b1, r1, h0, extra0, 1,
                                               out, nullptr, hf, extraf);
}